// round 7
// baseline (speedup 1.0000x reference)
#include <cuda_runtime.h>
#include <cstdint>

// Problem constants (fixed by the dataset)
#define NPTS   120000
#define DD     41
#define HH     1024
#define WW     1024
#define HBITS  18
#define HSZ    (1 << HBITS)
#define HMASK  (HSZ - 1)
#define MAXP   (NPTS * 26)

// ---------------- static device scratch (no allocations allowed) ----------------
__device__ int   g_hkey[HSZ];
__device__ int   g_hval[HSZ];
__device__ int   g_npairs;
__device__ int2  g_pairs[MAXP];
__device__ float g_bufA[NPTS * 64];
__device__ float g_bufB[NPTS * 64];

// ---------------- f32x2 packed math (Blackwell; ptxas never auto-fuses) ---------
__device__ __forceinline__ unsigned long long f2fma(unsigned long long a,
                                                    unsigned long long b,
                                                    unsigned long long c) {
    unsigned long long d;
    asm("fma.rn.f32x2 %0, %1, %2, %3;" : "=l"(d) : "l"(a), "l"(b), "l"(c));
    return d;
}
__device__ __forceinline__ unsigned long long f2add(unsigned long long a,
                                                    unsigned long long b) {
    unsigned long long d;
    asm("add.rn.f32x2 %0, %1, %2;" : "=l"(d) : "l"(a), "l"(b));
    return d;
}
__device__ __forceinline__ unsigned long long f2splat(float x) {
    unsigned long long d;
    asm("mov.b64 %0, {%1, %1};" : "=l"(d) : "r"(__float_as_int(x)));
    return d;
}

__device__ __forceinline__ unsigned hashf(int key) {
    return ((unsigned)key * 2654435761u) >> (32 - HBITS);
}

// ---------------- rulebook build ----------------
__global__ void k_clear() {
    int i = blockIdx.x * blockDim.x + threadIdx.x;
    if (i < HSZ) g_hkey[i] = -1;
    if (i == 0) g_npairs = 0;
}

__global__ void k_insert(const int* __restrict__ coors, int n) {
    int i = blockIdx.x * blockDim.x + threadIdx.x;
    if (i >= n) return;
    int4 c = ((const int4*)coors)[i];
    int key = ((c.x * DD + c.y) * HH + c.z) * WW + c.w;
    unsigned s = hashf(key) & HMASK;
    while (true) {
        int old = atomicCAS(&g_hkey[s], -1, key);
        if (old == -1) { g_hval[s] = i; break; }
        s = (s + 1) & HMASK;
    }
}

// one thread per (point, tap). Center tap (k=13) is handled by the dense GEMM.
__global__ void k_pairs(const int* __restrict__ coors, int n) {
    int idx = blockIdx.x * blockDim.x + threadIdx.x;
    if (idx >= n * 27) return;
    int i = idx / 27;
    int k = idx - i * 27;
    if (k == 13) return;
    int dz = k / 9 - 1, dy = (k / 3) % 3 - 1, dx = k % 3 - 1;
    int4 c = ((const int4*)coors)[i];
    int z = c.y + dz, y = c.z + dy, x = c.w + dx;
    if (z < 0 || z >= DD || y < 0 || y >= HH || x < 0 || x >= WW) return;
    int key = ((c.x * DD + z) * HH + y) * WW + x;
    unsigned s = hashf(key) & HMASK;
    int j = -1;
    while (true) {
        int kk = g_hkey[s];
        if (kk == key) { j = g_hval[s]; break; }
        if (kk == -1) break;
        s = (s + 1) & HMASK;
    }
    if (j < 0) return;
    int slot = atomicAdd(&g_npairs, 1);
    if (slot < MAXP) g_pairs[slot] = make_int2(i, (j << 5) | k);
}

// ---------------- dense center GEMM:  y[N,64] = x[N,64] @ Wc[64,64] ----------------
// Block: 256 thr (8 warps), 64 points/block. Warp handles 2 points at a time
// (half-warp per point); lane's u = lane&15 owns couts 4u..4u+3 via f32x2 pairs.
#define WPSTRIDE 65   // ulonglong2 row stride (4u*65*16B -> conflict-free phases)

__global__ __launch_bounds__(256, 4)
void k_gemm(const float* __restrict__ xg, const float* __restrict__ Wc,
            float* __restrict__ yg, int n) {
    __shared__ float4      sx[64 * 16];                 // 64 points x 64 floats
    __shared__ ulonglong2  swp[16 * WPSTRIDE];          // [u][cin]: 2 f32x2 w-pairs

    int tid = threadIdx.x;

    // Stage weights: swp[u][cin] = W[cin][4u..4u+3] reinterpreted as 2 f32x2.
    const float4* W4 = (const float4*)Wc;               // 64 rows x 16 float4
    #pragma unroll
    for (int j = 0; j < 4; j++) {
        int lin = tid + 256 * j;                        // 1024 float4 entries
        int cin = lin >> 4, u = lin & 15;
        float4 w = W4[lin];
        ulonglong2 v;
        v.x = ((unsigned long long)__float_as_uint(w.y) << 32) | __float_as_uint(w.x);
        v.y = ((unsigned long long)__float_as_uint(w.w) << 32) | __float_as_uint(w.z);
        swp[u * WPSTRIDE + cin] = v;
    }

    // Stage x tile (coalesced float4 stream).
    long base = (long)blockIdx.x * 64;
    const float4* xg4 = (const float4*)xg + base * 16;
    int maxlin = (int)((long)n * 16 - base * 16);       // float4 entries remaining
    #pragma unroll
    for (int j = 0; j < 4; j++) {
        int lin = tid + 256 * j;
        sx[lin] = (lin < maxlin) ? xg4[lin] : make_float4(0.f, 0.f, 0.f, 0.f);
    }
    __syncthreads();

    int warp = tid >> 5, lane = tid & 31;
    int u = lane & 15, half = lane >> 4;
    const ulonglong2* wrow = &swp[u * WPSTRIDE];

    #pragma unroll
    for (int r = 0; r < 4; r++) {
        int p = warp * 8 + 2 * r + half;                // local point
        if (base + p >= n) continue;
        const float4* xr = &sx[p * 16];
        unsigned long long a0 = 0, a1 = 0, a2 = 0, a3 = 0;
        #pragma unroll
        for (int c4 = 0; c4 < 16; c4++) {
            float4 xv = xr[c4];
            ulonglong2 w0 = wrow[4 * c4 + 0];
            ulonglong2 w1 = wrow[4 * c4 + 1];
            ulonglong2 w2 = wrow[4 * c4 + 2];
            ulonglong2 w3 = wrow[4 * c4 + 3];
            unsigned long long s;
            s = f2splat(xv.x); a0 = f2fma(s, w0.x, a0); a1 = f2fma(s, w0.y, a1);
            s = f2splat(xv.y); a2 = f2fma(s, w1.x, a2); a3 = f2fma(s, w1.y, a3);
            s = f2splat(xv.z); a0 = f2fma(s, w2.x, a0); a1 = f2fma(s, w2.y, a1);
            s = f2splat(xv.w); a2 = f2fma(s, w3.x, a2); a3 = f2fma(s, w3.y, a3);
        }
        ulonglong2 o;
        o.x = f2add(a0, a2);   // couts 4u, 4u+1
        o.y = f2add(a1, a3);   // couts 4u+2, 4u+3
        ((ulonglong2*)(yg + (base + p) * 64))[u] = o;
    }
}

// ---------------- sparse correction: out[i] += x[j] @ W[l,k] for each pair --------
__global__ void k_apply_pairs(const float* __restrict__ xg,
                              const float* __restrict__ Wl,   // 27*64*64
                              float* __restrict__ yg) {
    int np = g_npairs;
    if (np > MAXP) np = MAXP;
    long total = (long)np * 64;
    for (long idx = blockIdx.x * (long)blockDim.x + threadIdx.x; idx < total;
         idx += (long)gridDim.x * blockDim.x) {
        int p = (int)(idx >> 6);
        int c = (int)(idx & 63);
        int2 pr = g_pairs[p];
        int i = pr.x, j = pr.y >> 5, k = pr.y & 31;
        const float* xr = xg + (long)j * 64;
        const float* w = Wl + k * 4096 + c;
        float acc = 0.f;
        #pragma unroll
        for (int cin = 0; cin < 64; cin++) acc = fmaf(xr[cin], w[cin * 64], acc);
        atomicAdd(&yg[(long)i * 64 + c], acc);
    }
}

// ---------------- launch ----------------
extern "C" void kernel_launch(void* const* d_in, const int* in_sizes, int n_in,
                              void* d_out, int out_size) {
    const float* features = (const float*)d_in[0];
    const float* Ws       = (const float*)d_in[1];
    const int*   coors    = (const int*)d_in[2];
    float*       out      = (float*)d_out;

    int n = in_sizes[0] / 64;
    if (n > NPTS) n = NPTS;

    // Rulebook (layer-invariant)
    k_clear<<<HSZ / 256, 256>>>();
    k_insert<<<(n + 255) / 256, 256>>>(coors, n);
    k_pairs<<<(n * 27 + 255) / 256, 256>>>(coors, n);

    int gblocks = (n + 63) / 64;
    const int PAIR_GRID = 1024, PAIR_BLK = 128;

    // Layer 0: features -> bufA
    k_gemm<<<gblocks, 256>>>(features, Ws + (0 * 27 + 13) * 4096, g_bufA, n);
    k_apply_pairs<<<PAIR_GRID, PAIR_BLK>>>(features, Ws + 0 * 27 * 4096, g_bufA);
    // Layer 1: bufA -> bufB
    k_gemm<<<gblocks, 256>>>(g_bufA, Ws + (1 * 27 + 13) * 4096, g_bufB, n);
    k_apply_pairs<<<PAIR_GRID, PAIR_BLK>>>(g_bufA, Ws + 1 * 27 * 4096, g_bufB);
    // Layer 2: bufB -> out
    k_gemm<<<gblocks, 256>>>(g_bufB, Ws + (2 * 27 + 13) * 4096, out, n);
    k_apply_pairs<<<PAIR_GRID, PAIR_BLK>>>(g_bufB, Ws + 2 * 27 * 4096, out);
}